// round 15
// baseline (speedup 1.0000x reference)
#include <cuda_runtime.h>
#include <cuda_fp16.h>
#include <cstdint>
#include <math.h>

#define T_TOK 4096
#define H_DIM 1024
#define F_DIM 2048
#define E_NUM 8
#define F2    (2 * F_DIM)

// ===================== helpers =====================
__device__ __forceinline__ uint32_t smem_u32(const void* p) {
    uint32_t a;
    asm("{ .reg .u64 t; cvta.to.shared.u64 t, %1; cvt.u32.u64 %0, t; }" : "=r"(a) : "l"(p));
    return a;
}
#define SW128(off) ((off) ^ (((off) >> 3) & 0x70))

__device__ __forceinline__ void cp_async16(uint32_t dst, const void* src, int srcBytes) {
    asm volatile("cp.async.cg.shared.global [%0], [%1], 16, %2;"
                 :: "r"(dst), "l"(src), "r"(srcBytes) : "memory");
}
#define CP_COMMIT() asm volatile("cp.async.commit_group;" ::: "memory")
#define CP_WAIT(n)  asm volatile("cp.async.wait_group %0;" :: "n"(n) : "memory")

__device__ __forceinline__ void ldsm4(uint32_t* r, uint32_t addr) {
    asm volatile("ldmatrix.sync.aligned.m8n8.x4.shared.b16 {%0,%1,%2,%3}, [%4];"
                 : "=r"(r[0]), "=r"(r[1]), "=r"(r[2]), "=r"(r[3]) : "r"(addr));
}

__device__ __forceinline__ void mma16816h(float* d, const uint32_t* a, uint32_t b0, uint32_t b1) {
    asm volatile("mma.sync.aligned.m16n8k16.row.col.f32.f16.f16.f32 "
                 "{%0,%1,%2,%3}, {%4,%5,%6,%7}, {%8,%9}, {%0,%1,%2,%3};"
                 : "+f"(d[0]), "+f"(d[1]), "+f"(d[2]), "+f"(d[3])
                 : "r"(a[0]), "r"(a[1]), "r"(a[2]), "r"(a[3]), "r"(b0), "r"(b1));
}

__device__ __forceinline__ uint32_t pack_h2(float x, float y) {
    __half2 t = __floats2half2_rn(x, y);
    return *(uint32_t*)&t;
}

// ===================== scratch =====================
__device__ __half g_x_h  [(size_t)T_TOK * H_DIM];
__device__ __half g_sw1t [(size_t)2 * F_DIM * H_DIM];
__device__ __half g_ew1t [(size_t)E_NUM * F_DIM * H_DIM];
__device__ __half g_sw2t [(size_t)2 * H_DIM * F_DIM];
__device__ __half g_ew2t [(size_t)E_NUM * H_DIM * F_DIM];
__device__ __half g_hids [(size_t)T_TOK * F2];
__device__ __half g_hidr [(size_t)2 * T_TOK * F_DIM];
__device__ float g_rout [(size_t)2 * T_TOK * H_DIM];
__device__ float g_part0[(size_t)T_TOK * H_DIM];
__device__ float g_part1[(size_t)T_TOK * H_DIM];
__device__ float g_zb[H_DIM];                 // static zero bias
__device__ int g_counts[E_NUM];
__device__ int g_list[E_NUM * T_TOK];
__device__ int g_tok_e[2 * T_TOK];
__device__ int g_tok_slot[2 * T_TOK];

// ===================== small kernels =====================
__global__ void router_kernel(const float* __restrict__ x,
                              const float* __restrict__ rw,
                              const float* __restrict__ rb) {
    int warp = (blockIdx.x * blockDim.x + threadIdx.x) >> 5;
    int lane = threadIdx.x & 31;
    if (warp >= T_TOK) return;
    const float* xp = x + (long)warp * H_DIM;
    float acc[E_NUM];
#pragma unroll
    for (int e = 0; e < E_NUM; e++) acc[e] = 0.f;
    for (int h = lane; h < H_DIM; h += 32) {
        float xv = xp[h];
        const float* w = rw + (long)h * E_NUM;
#pragma unroll
        for (int e = 0; e < E_NUM; e++) acc[e] = fmaf(xv, w[e], acc[e]);
    }
#pragma unroll
    for (int e = 0; e < E_NUM; e++)
#pragma unroll
        for (int off = 16; off; off >>= 1)
            acc[e] += __shfl_xor_sync(0xFFFFFFFFu, acc[e], off);
    if (lane == 0) {
        float lg[E_NUM];
#pragma unroll
        for (int e = 0; e < E_NUM; e++) lg[e] = acc[e] + rb[e];
        int e0 = 0;
#pragma unroll
        for (int e = 1; e < E_NUM; e++) if (lg[e] > lg[e0]) e0 = e;
        int e1 = -1;
#pragma unroll
        for (int e = 0; e < E_NUM; e++) {
            if (e == e0) continue;
            if (e1 < 0 || lg[e] > lg[e1]) e1 = e;
        }
        int sel[2] = { e0, e1 };
        int t = warp;
#pragma unroll
        for (int k = 0; k < 2; k++) {
            int e = sel[k];
            int slot = atomicAdd(&g_counts[e], 1);
            g_list[e * T_TOK + slot] = t;
            g_tok_e[2 * t + k] = e;
            g_tok_slot[2 * t + k] = slot;
        }
    }
}

// out = part0 + part1 + routed0 + routed1 (expert bases computed inline)
__global__ void combine_kernel(float* __restrict__ out) {
    __shared__ int sb[E_NUM];
    if (threadIdx.x < E_NUM) {
        int s = 0;
#pragma unroll
        for (int e = 0; e < E_NUM; e++) if (e < threadIdx.x) s += g_counts[e];
        sb[threadIdx.x] = s;
    }
    __syncthreads();
    int t = blockIdx.x;
    int e0 = g_tok_e[2 * t], e1 = g_tok_e[2 * t + 1];
    long r0 = (long)sb[e0] + g_tok_slot[2 * t];
    long r1 = (long)sb[e1] + g_tok_slot[2 * t + 1];
    int i = threadIdx.x;
    long ti = (long)t * (H_DIM / 4) + i;
    const float4 a = ((const float4*)g_part0)[ti];
    const float4 b = ((const float4*)g_part1)[ti];
    const float4 c = ((const float4*)g_rout)[r0 * (H_DIM / 4) + i];
    const float4 d = ((const float4*)g_rout)[r1 * (H_DIM / 4) + i];
    float4 o;
    o.x = a.x + b.x + c.x + d.x;
    o.y = a.y + b.y + c.y + d.y;
    o.z = a.z + b.z + c.z + d.z;
    o.w = a.w + b.w + c.w + d.w;
    ((float4*)out)[ti] = o;
}

// ===================== converters =====================
// x fp32 -> fp16; also zeroes g_counts (runs before router)
__global__ void split_kernel(const float* __restrict__ in,
                             __half* __restrict__ hi, int n4) {
    if (blockIdx.x == 0 && threadIdx.x < E_NUM) g_counts[threadIdx.x] = 0;
    int i = blockIdx.x * blockDim.x + threadIdx.x;
    if (i >= n4) return;
    float4 v = ((const float4*)in)[i];
    union { __half b[4]; uint2 u; } hb;
    hb.b[0] = __float2half_rn(v.x);
    hb.b[1] = __float2half_rn(v.y);
    hb.b[2] = __float2half_rn(v.z);
    hb.b[3] = __float2half_rn(v.w);
    ((uint2*)hi)[i] = hb.u;
}

__global__ void tsplitG1(const float* __restrict__ sw1, const float* __restrict__ ew1) {
    __shared__ float t[32][33];
    int z = blockIdx.z;
    const float* src;
    __half* hi;
    if (z < E_NUM) {
        src = ew1 + (size_t)z * H_DIM * F_DIM;
        hi = g_ew1t + (size_t)z * F_DIM * H_DIM;
    } else {
        int n = z - E_NUM;
        src = sw1 + (size_t)n * H_DIM * F_DIM;
        hi = g_sw1t + (size_t)n * F_DIM * H_DIM;
    }
    int n0 = blockIdx.x * 32, k0 = blockIdx.y * 32;
    int tx = threadIdx.x, ty = threadIdx.y;
#pragma unroll
    for (int i = 0; i < 32; i += 8)
        t[ty + i][tx] = src[(long)(k0 + ty + i) * F_DIM + n0 + tx];
    __syncthreads();
#pragma unroll
    for (int i = 0; i < 32; i += 8)
        hi[(long)(n0 + ty + i) * H_DIM + k0 + tx] = __float2half_rn(t[tx][ty + i]);
}

__global__ void tsplitG2(const float* __restrict__ sw2, const float* __restrict__ ew2) {
    __shared__ float t[32][33];
    int z = blockIdx.z;
    const float* src;
    __half* hi;
    if (z < E_NUM) {
        src = ew2 + (size_t)z * F_DIM * H_DIM;
        hi = g_ew2t + (size_t)z * H_DIM * F_DIM;
    } else {
        int n = z - E_NUM;
        src = sw2 + (size_t)n * F_DIM * H_DIM;
        hi = g_sw2t + (size_t)n * H_DIM * F_DIM;
    }
    int n0 = blockIdx.x * 32, k0 = blockIdx.y * 32;
    int tx = threadIdx.x, ty = threadIdx.y;
#pragma unroll
    for (int i = 0; i < 32; i += 8)
        t[ty + i][tx] = src[(long)(k0 + ty + i) * H_DIM + n0 + tx];
    __syncthreads();
#pragma unroll
    for (int i = 0; i < 32; i += 8)
        hi[(long)(n0 + ty + i) * F_DIM + k0 + tx] = __float2half_rn(t[tx][ty + i]);
}

// ===================== GEMM core: CTA 64x128, 256 thr, warp 32x32 ==========
// fp16 single product: C = A @ B^T.  BK=64 (128B K-major rows).
// Stage = A 8KB + B 16KB = 24KB; 3 stages; prefetch depth 2; one sync/chunk.
// 3 CTAs/SM (reg cap 85) -> 24 warps/SM.
#define STAGE_BYTES 24576
#define B_OFF 8192
#define DSMEM_BYTES (3 * STAGE_BYTES)

template<bool GELU>
__device__ __forceinline__ void gemm_core(
    const __half* __restrict__ Ah, const __half* __restrict__ Bh,
    const float* __restrict__ bias, const float* __restrict__ bias2,
    __half* Ch, float* Cf,
    int M, int K, int ldA, int ldc, int colOff, const int* list, int rowBase)
{
    int colBase = blockIdx.y * 128;
    extern __shared__ char smem[];
    uint32_t sbase = smem_u32(smem);
    int tid = threadIdx.x;
    int wid = tid >> 5, lane = tid & 31;
    int warpM = wid & 1, warpN = wid >> 1;   // 2m x 4n, warp tile 32x32

    // ---- loader metadata: 2 A units + 4 B units per thread ----
    int c = tid & 7;                 // 16B chunk within 128B row
    int kel = c * 8;                 // fp16 elem offset within 64-wide K chunk
    int r0 = tid >> 3;               // 0..31
    uint32_t swr = SW128((uint32_t)(r0 * 128 + c * 16));
    const __half* aSrc[2]; uint32_t aOk = 0;
#pragma unroll
    for (int i = 0; i < 2; i++) {
        int gR = rowBase + r0 + 32 * i;
        bool ok = gR < M;
        if (ok) aOk |= (1u << i);
        long rrow = list ? (ok ? list[gR] : 0) : (ok ? gR : 0);
        aSrc[i] = Ah + rrow * ldA + kel;
    }
    const __half* bSrc[4];
#pragma unroll
    for (int i = 0; i < 4; i++)
        bSrc[i] = Bh + (long)(colBase + r0 + 32 * i) * K + kel;

    const int NC = K >> 6;
    auto issue = [&](int ci) {
        uint32_t st = sbase + (uint32_t)(ci % 3) * STAGE_BYTES;
        int kbase = ci << 6;
#pragma unroll
        for (int i = 0; i < 2; i++)
            cp_async16(st + swr + 4096u * i, aSrc[i] + kbase,
                       (aOk >> i) & 1 ? 16 : 0);
#pragma unroll
        for (int i = 0; i < 4; i++)
            cp_async16(st + B_OFF + swr + 4096u * i, bSrc[i] + kbase, 16);
        CP_COMMIT();
    };

    float acc[2][4][4];
#pragma unroll
    for (int mi = 0; mi < 2; mi++)
#pragma unroll
        for (int nj = 0; nj < 4; nj++)
#pragma unroll
            for (int u = 0; u < 4; u++) acc[mi][nj][u] = 0.f;

    int lrow = lane & 15;
    int lc16 = (lane >> 4) * 16;
    uint32_t swA[2], swB[2];
#pragma unroll
    for (int mi = 0; mi < 2; mi++)
        swA[mi] = SW128((uint32_t)((warpM * 32 + mi * 16 + lrow) * 128 + lc16));
#pragma unroll
    for (int g = 0; g < 2; g++)
        swB[g] = B_OFF + SW128((uint32_t)((warpN * 32 + g * 16 + lrow) * 128 + lc16));

    issue(0); issue(1);
    for (int ci = 0; ci < NC; ci++) {
        CP_WAIT(1);
        __syncthreads();
        if (ci + 2 < NC) issue(ci + 2);
        else CP_COMMIT();
        uint32_t st = sbase + (uint32_t)(ci % 3) * STAGE_BYTES;
#pragma unroll
        for (int ks = 0; ks < 4; ks++) {
            uint32_t koff = ks * 32;
            uint32_t a[2][4];
#pragma unroll
            for (int mi = 0; mi < 2; mi++)
                ldsm4(a[mi], st + (swA[mi] ^ koff));
#pragma unroll
            for (int g = 0; g < 2; g++) {
                uint32_t b[4];
                ldsm4(b, st + (swB[g] ^ koff));
#pragma unroll
                for (int mi = 0; mi < 2; mi++) {
                    mma16816h(acc[mi][2 * g + 0], a[mi], b[0], b[2]);
                    mma16816h(acc[mi][2 * g + 1], a[mi], b[1], b[3]);
                }
            }
        }
    }

    // epilogue
    int rw0 = rowBase + warpM * 32 + (lane >> 2);
    int cw0 = colBase + warpN * 32 + (lane & 3) * 2;
#pragma unroll
    for (int mi = 0; mi < 2; mi++) {
#pragma unroll
        for (int nj = 0; nj < 4; nj++) {
            int col = cw0 + nj * 8;
            float b0 = bias[col], b1 = bias[col + 1];
            if (bias2) { b0 += bias2[col]; b1 += bias2[col + 1]; }
#pragma unroll
            for (int h = 0; h < 2; h++) {
                int row_ = rw0 + mi * 16 + h * 8;
                if (row_ < M) {
                    float v0 = acc[mi][nj][2 * h + 0] + b0;
                    float v1 = acc[mi][nj][2 * h + 1] + b1;
                    long off = (long)row_ * ldc + colOff + col;
                    if (GELU) {
                        float g0 = 0.5f * v0 * (1.0f + erff(v0 * 0.70710678118654752f));
                        float g1 = 0.5f * v1 * (1.0f + erff(v1 * 0.70710678118654752f));
                        *(uint32_t*)(Ch + off) = pack_h2(g0, g1);
                    } else {
                        float2 v; v.x = v0; v.y = v1;
                        *(float2*)(Cf + off) = v;
                    }
                }
            }
        }
    }
}

// GEMM1 merged: z<8 routed expert z (gather); z>=8 shared n=z-8.
__global__ __launch_bounds__(256, 3)
void moe_gemm1(const float* __restrict__ sb1, const float* __restrict__ eb1)
{
    __shared__ int sMB[2];
    int z = blockIdx.z;
    if (threadIdx.x == 0) {
        if (z < E_NUM) {
            int s = 0;
#pragma unroll
            for (int e = 0; e < E_NUM; e++) if (e < z) s += g_counts[e];
            sMB[0] = g_counts[z]; sMB[1] = s;
        } else { sMB[0] = T_TOK; sMB[1] = 0; }
    }
    __syncthreads();
    int M = sMB[0];
    long b = sMB[1];
    int ldc, colOff;
    const int* list;
    const __half* Bh;
    const float* bias;
    __half* Ch;
    if (z < E_NUM) {
        list = g_list + (long)z * T_TOK;
        Bh = g_ew1t + (size_t)z * F_DIM * H_DIM;
        bias = eb1 + z * F_DIM;
        Ch = g_hidr + b * F_DIM;
        ldc = F_DIM; colOff = 0;
    } else {
        int n = z - E_NUM;
        list = nullptr;
        Bh = g_sw1t + (size_t)n * F_DIM * H_DIM;
        bias = sb1 + n * F_DIM;
        Ch = g_hids;
        ldc = F2; colOff = n * F_DIM;
    }
    int rowBase = blockIdx.x * 64;
    if (rowBase >= M) return;
    gemm_core<true>(g_x_h, Bh, bias, nullptr, Ch, nullptr,
                    M, H_DIM, H_DIM, ldc, colOff, list, rowBase);
}

// GEMM2: 10 uniform K=2048 slices. z<8 routed; z=8/9 shared halves.
__global__ __launch_bounds__(256, 3)
void moe_gemm2(const float* __restrict__ sb2, const float* __restrict__ eb2)
{
    __shared__ int sMB[2];
    int z = blockIdx.z;
    if (threadIdx.x == 0) {
        if (z < E_NUM) {
            int s = 0;
#pragma unroll
            for (int e = 0; e < E_NUM; e++) if (e < z) s += g_counts[e];
            sMB[0] = g_counts[z]; sMB[1] = s;
        } else { sMB[0] = T_TOK; sMB[1] = 0; }
    }
    __syncthreads();
    int M = sMB[0];
    long b = sMB[1];
    int ldA;
    const __half *Ah, *Bh;
    const float *bias, *bias2;
    float* Cf;
    if (z < E_NUM) {
        Ah = g_hidr + b * F_DIM;
        ldA = F_DIM;
        Bh = g_ew2t + (size_t)z * H_DIM * F_DIM;
        bias = eb2 + z * H_DIM; bias2 = nullptr;
        Cf = g_rout + b * H_DIM;
    } else if (z == E_NUM) {
        Ah = g_hids; ldA = F2;
        Bh = g_sw2t;
        bias = sb2; bias2 = sb2 + H_DIM;
        Cf = g_part0;
    } else {
        Ah = g_hids + F_DIM; ldA = F2;
        Bh = g_sw2t + (size_t)H_DIM * F_DIM;
        bias = g_zb; bias2 = nullptr;
        Cf = g_part1;
    }
    int rowBase = blockIdx.x * 64;
    if (rowBase >= M) return;
    gemm_core<false>(Ah, Bh, bias, bias2, nullptr, Cf,
                     M, F_DIM, ldA, H_DIM, 0, nullptr, rowBase);
}

// ===================== launch =====================
extern "C" void kernel_launch(void* const* d_in, const int* in_sizes, int n_in,
                              void* d_out, int out_size)
{
    const float* x   = (const float*)d_in[0];
    const float* sw1 = (const float*)d_in[1];
    const float* sb1 = (const float*)d_in[2];
    const float* sw2 = (const float*)d_in[3];
    const float* sb2 = (const float*)d_in[4];
    const float* ew1 = (const float*)d_in[5];
    const float* eb1 = (const float*)d_in[6];
    const float* ew2 = (const float*)d_in[7];
    const float* eb2 = (const float*)d_in[8];
    const float* rw  = (const float*)d_in[9];
    const float* rb  = (const float*)d_in[10];
    float* out = (float*)d_out;

    __half* x_h;
    cudaGetSymbolAddress((void**)&x_h, g_x_h);

    cudaFuncSetAttribute(moe_gemm1, cudaFuncAttributeMaxDynamicSharedMemorySize, DSMEM_BYTES);
    cudaFuncSetAttribute(moe_gemm2, cudaFuncAttributeMaxDynamicSharedMemorySize, DSMEM_BYTES);

    // 1: x conversion + counts zero
    split_kernel<<<(T_TOK * H_DIM / 4 + 255) / 256, 256>>>(x, x_h, T_TOK * H_DIM / 4);
    // 2: w1 transpose+convert
    tsplitG1<<<dim3(F_DIM / 32, H_DIM / 32, E_NUM + 2), dim3(32, 8)>>>(sw1, ew1);
    // 3: router
    router_kernel<<<T_TOK / 4, 128>>>(x, rw, rb);
    // 4 (PROFILED): merged GEMM1
    moe_gemm1<<<dim3(T_TOK / 64, F_DIM / 128, E_NUM + 2), 256, DSMEM_BYTES>>>(sb1, eb1);
    // 5: w2 transpose+convert
    tsplitG2<<<dim3(H_DIM / 32, F_DIM / 32, E_NUM + 2), dim3(32, 8)>>>(sw2, ew2);
    // 6: GEMM2, 10 uniform slices
    moe_gemm2<<<dim3(T_TOK / 64, H_DIM / 128, E_NUM + 2), 256, DSMEM_BYTES>>>(sb2, eb2);
    // 7: combine
    combine_kernel<<<T_TOK, 256>>>(out);
}

// round 17
// speedup vs baseline: 1.2893x; 1.2893x over previous
#include <cuda_runtime.h>
#include <cuda_fp16.h>
#include <cstdint>
#include <math.h>

#define T_TOK 4096
#define H_DIM 1024
#define F_DIM 2048
#define E_NUM 8
#define F2    (2 * F_DIM)

// ===================== helpers =====================
__device__ __forceinline__ uint32_t smem_u32(const void* p) {
    uint32_t a;
    asm("{ .reg .u64 t; cvta.to.shared.u64 t, %1; cvt.u32.u64 %0, t; }" : "=r"(a) : "l"(p));
    return a;
}
#define SW128(off) ((off) ^ (((off) >> 3) & 0x70))

__device__ __forceinline__ void cp_async16(uint32_t dst, const void* src, int srcBytes) {
    asm volatile("cp.async.cg.shared.global [%0], [%1], 16, %2;"
                 :: "r"(dst), "l"(src), "r"(srcBytes) : "memory");
}
#define CP_COMMIT() asm volatile("cp.async.commit_group;" ::: "memory")
#define CP_WAIT(n)  asm volatile("cp.async.wait_group %0;" :: "n"(n) : "memory")

__device__ __forceinline__ void ldsm4(uint32_t* r, uint32_t addr) {
    asm volatile("ldmatrix.sync.aligned.m8n8.x4.shared.b16 {%0,%1,%2,%3}, [%4];"
                 : "=r"(r[0]), "=r"(r[1]), "=r"(r[2]), "=r"(r[3]) : "r"(addr));
}

__device__ __forceinline__ void mma16816h(float* d, const uint32_t* a, uint32_t b0, uint32_t b1) {
    asm volatile("mma.sync.aligned.m16n8k16.row.col.f32.f16.f16.f32 "
                 "{%0,%1,%2,%3}, {%4,%5,%6,%7}, {%8,%9}, {%0,%1,%2,%3};"
                 : "+f"(d[0]), "+f"(d[1]), "+f"(d[2]), "+f"(d[3])
                 : "r"(a[0]), "r"(a[1]), "r"(a[2]), "r"(a[3]), "r"(b0), "r"(b1));
}

__device__ __forceinline__ uint32_t pack_h2(float x, float y) {
    __half2 t = __floats2half2_rn(x, y);
    return *(uint32_t*)&t;
}

// ===================== scratch =====================
__device__ __half g_x_h  [(size_t)T_TOK * H_DIM];
__device__ __half g_sw1t [(size_t)2 * F_DIM * H_DIM];
__device__ __half g_ew1t [(size_t)E_NUM * F_DIM * H_DIM];
__device__ __half g_sw2t [(size_t)2 * H_DIM * F_DIM];
__device__ __half g_ew2t [(size_t)E_NUM * H_DIM * F_DIM];
__device__ __half g_hids [(size_t)T_TOK * F2];
__device__ __half g_hidr [(size_t)2 * T_TOK * F_DIM];
__device__ float g_rout [(size_t)2 * T_TOK * H_DIM];
__device__ float g_part0[(size_t)T_TOK * H_DIM];
__device__ float g_part1[(size_t)T_TOK * H_DIM];
__device__ float g_zb[H_DIM];                 // static zero bias
__device__ int g_counts[E_NUM];
__device__ int g_base[E_NUM];
__device__ int g_list[E_NUM * T_TOK];
__device__ int g_tok_e[2 * T_TOK];
__device__ int g_tok_slot[2 * T_TOK];

// ===================== small kernels =====================
__global__ void router_kernel(const float* __restrict__ x,
                              const float* __restrict__ rw,
                              const float* __restrict__ rb) {
    int warp = (blockIdx.x * blockDim.x + threadIdx.x) >> 5;
    int lane = threadIdx.x & 31;
    if (warp >= T_TOK) return;
    const float* xp = x + (long)warp * H_DIM;
    float acc[E_NUM];
#pragma unroll
    for (int e = 0; e < E_NUM; e++) acc[e] = 0.f;
    for (int h = lane; h < H_DIM; h += 32) {
        float xv = xp[h];
        const float* w = rw + (long)h * E_NUM;
#pragma unroll
        for (int e = 0; e < E_NUM; e++) acc[e] = fmaf(xv, w[e], acc[e]);
    }
#pragma unroll
    for (int e = 0; e < E_NUM; e++)
#pragma unroll
        for (int off = 16; off; off >>= 1)
            acc[e] += __shfl_xor_sync(0xFFFFFFFFu, acc[e], off);
    if (lane == 0) {
        float lg[E_NUM];
#pragma unroll
        for (int e = 0; e < E_NUM; e++) lg[e] = acc[e] + rb[e];
        int e0 = 0;
#pragma unroll
        for (int e = 1; e < E_NUM; e++) if (lg[e] > lg[e0]) e0 = e;
        int e1 = -1;
#pragma unroll
        for (int e = 0; e < E_NUM; e++) {
            if (e == e0) continue;
            if (e1 < 0 || lg[e] > lg[e1]) e1 = e;
        }
        int sel[2] = { e0, e1 };
        int t = warp;
#pragma unroll
        for (int k = 0; k < 2; k++) {
            int e = sel[k];
            int slot = atomicAdd(&g_counts[e], 1);
            g_list[e * T_TOK + slot] = t;
            g_tok_e[2 * t + k] = e;
            g_tok_slot[2 * t + k] = slot;
        }
    }
}

__global__ void base_kernel() {
    if (threadIdx.x == 0) {
        int s = 0;
#pragma unroll
        for (int e = 0; e < E_NUM; e++) { g_base[e] = s; s += g_counts[e]; }
    }
}

// out = part0 + part1 + routed0 + routed1
__global__ void combine_kernel(float* __restrict__ out) {
    int t = blockIdx.x;
    int e0 = g_tok_e[2 * t], e1 = g_tok_e[2 * t + 1];
    long r0 = (long)g_base[e0] + g_tok_slot[2 * t];
    long r1 = (long)g_base[e1] + g_tok_slot[2 * t + 1];
    int i = threadIdx.x;
    long ti = (long)t * (H_DIM / 4) + i;
    const float4 a = ((const float4*)g_part0)[ti];
    const float4 b = ((const float4*)g_part1)[ti];
    const float4 c = ((const float4*)g_rout)[r0 * (H_DIM / 4) + i];
    const float4 d = ((const float4*)g_rout)[r1 * (H_DIM / 4) + i];
    float4 o;
    o.x = a.x + b.x + c.x + d.x;
    o.y = a.y + b.y + c.y + d.y;
    o.z = a.z + b.z + c.z + d.z;
    o.w = a.w + b.w + c.w + d.w;
    ((float4*)out)[ti] = o;
}

// ===================== converters =====================
// x fp32 -> fp16; block 0 also zeroes g_counts (must run before router)
__global__ void split_kernel(const float* __restrict__ in,
                             __half* __restrict__ hi, int n4) {
    if (blockIdx.x == 0 && threadIdx.x < E_NUM) g_counts[threadIdx.x] = 0;
    int i = blockIdx.x * blockDim.x + threadIdx.x;
    if (i >= n4) return;
    float4 v = ((const float4*)in)[i];
    union { __half b[4]; uint2 u; } hb;
    hb.b[0] = __float2half_rn(v.x);
    hb.b[1] = __float2half_rn(v.y);
    hb.b[2] = __float2half_rn(v.z);
    hb.b[3] = __float2half_rn(v.w);
    ((uint2*)hi)[i] = hb.u;
}

// w1 [H][F] per slice -> K-major [F][H] half. z<8: ew1[z]; z>=8: sw1[z-8].
// half2 (4B) coalesced stores.
__global__ void tsplitG1(const float* __restrict__ sw1, const float* __restrict__ ew1) {
    __shared__ float t[32][33];
    int z = blockIdx.z;
    const float* src;
    __half* hi;
    if (z < E_NUM) {
        src = ew1 + (size_t)z * H_DIM * F_DIM;
        hi = g_ew1t + (size_t)z * F_DIM * H_DIM;
    } else {
        int n = z - E_NUM;
        src = sw1 + (size_t)n * H_DIM * F_DIM;
        hi = g_sw1t + (size_t)n * F_DIM * H_DIM;
    }
    int n0 = blockIdx.x * 32, k0 = blockIdx.y * 32;
    int tx = threadIdx.x, ty = threadIdx.y;
#pragma unroll
    for (int i = 0; i < 32; i += 8)
        t[ty + i][tx] = src[(long)(k0 + ty + i) * F_DIM + n0 + tx];
    __syncthreads();
#pragma unroll
    for (int j = 0; j < 2; j++) {
        int u = j * 256 + ty * 32 + tx;
        int n = u >> 4;           // 0..31
        int kp = u & 15;          // half2 index: k = 2*kp
        __half2 v = __floats2half2_rn(t[2 * kp][n], t[2 * kp + 1][n]);
        *(__half2*)(hi + (long)(n0 + n) * H_DIM + k0 + 2 * kp) = v;
    }
}

// w2 [F][H] per slice -> K-major [H][F] half. z<8: ew2[z]; z>=8: sw2[z-8].
__global__ void tsplitG2(const float* __restrict__ sw2, const float* __restrict__ ew2) {
    __shared__ float t[32][33];
    int z = blockIdx.z;
    const float* src;
    __half* hi;
    if (z < E_NUM) {
        src = ew2 + (size_t)z * F_DIM * H_DIM;
        hi = g_ew2t + (size_t)z * H_DIM * F_DIM;
    } else {
        int n = z - E_NUM;
        src = sw2 + (size_t)n * F_DIM * H_DIM;
        hi = g_sw2t + (size_t)n * H_DIM * F_DIM;
    }
    int n0 = blockIdx.x * 32, k0 = blockIdx.y * 32;
    int tx = threadIdx.x, ty = threadIdx.y;
#pragma unroll
    for (int i = 0; i < 32; i += 8)
        t[ty + i][tx] = src[(long)(k0 + ty + i) * H_DIM + n0 + tx];
    __syncthreads();
#pragma unroll
    for (int j = 0; j < 2; j++) {
        int u = j * 256 + ty * 32 + tx;
        int n = u >> 4;
        int kp = u & 15;
        __half2 v = __floats2half2_rn(t[2 * kp][n], t[2 * kp + 1][n]);
        *(__half2*)(hi + (long)(n0 + n) * F_DIM + k0 + 2 * kp) = v;
    }
}

// ===================== GEMM core: CTA 128x128, 256 thr, warp 32x64 ==========
// fp16 single product: C = A @ B^T.  BK=64 (128B K-major rows).
// Stage = A 16KB + B 16KB = 32KB; 3 stages; prefetch depth 2; one sync/chunk.
#define STAGE_BYTES 32768
#define B_OFF 16384
#define DSMEM_BYTES (3 * STAGE_BYTES)

template<bool GELU>
__device__ __forceinline__ void gemm_core(
    const __half* __restrict__ Ah, const __half* __restrict__ Bh,
    const float* __restrict__ bias, const float* __restrict__ bias2,
    __half* Ch, float* Cf,
    int M, int K, int ldA, int ldc, int colOff, const int* list, int rowBase)
{
    int colBase = blockIdx.y * 128;
    extern __shared__ char smem[];
    uint32_t sbase = smem_u32(smem);
    int tid = threadIdx.x;
    int wid = tid >> 5, lane = tid & 31;
    int warpM = wid & 3, warpN = wid >> 2;   // 4m x 2n, warp tile 32x64

    // ---- loader metadata: 4 A units + 4 B units per thread ----
    int c = tid & 7;                 // 16B chunk within 128B row
    int kel = c * 8;                 // fp16 elem offset within 64-wide K chunk
    int r0 = tid >> 3;               // 0..31
    uint32_t swr = SW128((uint32_t)(r0 * 128 + c * 16));
    const __half* aSrc[4]; uint32_t aOk = 0;
#pragma unroll
    for (int i = 0; i < 4; i++) {
        int gR = rowBase + r0 + 32 * i;
        bool ok = gR < M;
        if (ok) aOk |= (1u << i);
        long rrow = list ? (ok ? list[gR] : 0) : (ok ? gR : 0);
        aSrc[i] = Ah + rrow * ldA + kel;
    }
    const __half* bSrc[4];
#pragma unroll
    for (int i = 0; i < 4; i++)
        bSrc[i] = Bh + (long)(colBase + r0 + 32 * i) * K + kel;

    const int NC = K >> 6;
    auto issue = [&](int ci) {
        uint32_t st = sbase + (uint32_t)(ci % 3) * STAGE_BYTES;
        int kbase = ci << 6;
#pragma unroll
        for (int i = 0; i < 4; i++)
            cp_async16(st + swr + 4096u * i, aSrc[i] + kbase,
                       (aOk >> i) & 1 ? 16 : 0);
#pragma unroll
        for (int i = 0; i < 4; i++)
            cp_async16(st + B_OFF + swr + 4096u * i, bSrc[i] + kbase, 16);
        CP_COMMIT();
    };

    float acc[2][8][4];
#pragma unroll
    for (int mi = 0; mi < 2; mi++)
#pragma unroll
        for (int nj = 0; nj < 8; nj++)
#pragma unroll
            for (int u = 0; u < 4; u++) acc[mi][nj][u] = 0.f;

    int lrow = lane & 15;
    int lc16 = (lane >> 4) * 16;
    uint32_t swA[2], swB[4];
#pragma unroll
    for (int mi = 0; mi < 2; mi++)
        swA[mi] = SW128((uint32_t)((warpM * 32 + mi * 16 + lrow) * 128 + lc16));
#pragma unroll
    for (int g = 0; g < 4; g++)
        swB[g] = B_OFF + SW128((uint32_t)((warpN * 64 + g * 16 + lrow) * 128 + lc16));

    issue(0); issue(1);
    for (int ci = 0; ci < NC; ci++) {
        CP_WAIT(1);
        __syncthreads();
        if (ci + 2 < NC) issue(ci + 2);
        else CP_COMMIT();
        uint32_t st = sbase + (uint32_t)(ci % 3) * STAGE_BYTES;
#pragma unroll
        for (int ks = 0; ks < 4; ks++) {
            uint32_t koff = ks * 32;
            uint32_t a[2][4];
#pragma unroll
            for (int mi = 0; mi < 2; mi++)
                ldsm4(a[mi], st + (swA[mi] ^ koff));
#pragma unroll
            for (int g = 0; g < 4; g++) {
                uint32_t b[4];
                ldsm4(b, st + (swB[g] ^ koff));
#pragma unroll
                for (int mi = 0; mi < 2; mi++) {
                    mma16816h(acc[mi][2 * g + 0], a[mi], b[0], b[2]);
                    mma16816h(acc[mi][2 * g + 1], a[mi], b[1], b[3]);
                }
            }
        }
    }

    // epilogue
    int rw0 = rowBase + warpM * 32 + (lane >> 2);
    int cw0 = colBase + warpN * 64 + (lane & 3) * 2;
#pragma unroll
    for (int mi = 0; mi < 2; mi++) {
#pragma unroll
        for (int nj = 0; nj < 8; nj++) {
            int col = cw0 + nj * 8;
            float b0 = bias[col], b1 = bias[col + 1];
            if (bias2) { b0 += bias2[col]; b1 += bias2[col + 1]; }
#pragma unroll
            for (int h = 0; h < 2; h++) {
                int row_ = rw0 + mi * 16 + h * 8;
                if (row_ < M) {
                    float v0 = acc[mi][nj][2 * h + 0] + b0;
                    float v1 = acc[mi][nj][2 * h + 1] + b1;
                    long off = (long)row_ * ldc + colOff + col;
                    if (GELU) {
                        float g0 = 0.5f * v0 * (1.0f + erff(v0 * 0.70710678118654752f));
                        float g1 = 0.5f * v1 * (1.0f + erff(v1 * 0.70710678118654752f));
                        *(uint32_t*)(Ch + off) = pack_h2(g0, g1);
                    } else {
                        float2 v; v.x = v0; v.y = v1;
                        *(float2*)(Cf + off) = v;
                    }
                }
            }
        }
    }
}

// GEMM1 merged: z<8 routed expert z (gather); z>=8 shared n=z-8.
__global__ __launch_bounds__(256, 2)
void moe_gemm1(const float* __restrict__ sb1, const float* __restrict__ eb1)
{
    int z = blockIdx.z;
    int M, ldc, colOff;
    const int* list;
    const __half* Bh;
    const float* bias;
    __half* Ch;
    if (z < E_NUM) {
        M = g_counts[z];
        list = g_list + (long)z * T_TOK;
        Bh = g_ew1t + (size_t)z * F_DIM * H_DIM;
        bias = eb1 + z * F_DIM;
        Ch = g_hidr + (long)g_base[z] * F_DIM;
        ldc = F_DIM; colOff = 0;
    } else {
        int n = z - E_NUM;
        M = T_TOK;
        list = nullptr;
        Bh = g_sw1t + (size_t)n * F_DIM * H_DIM;
        bias = sb1 + n * F_DIM;
        Ch = g_hids;
        ldc = F2; colOff = n * F_DIM;
    }
    int rowBase = blockIdx.x * 128;
    if (rowBase >= M) return;
    gemm_core<true>(g_x_h, Bh, bias, nullptr, Ch, nullptr,
                    M, H_DIM, H_DIM, ldc, colOff, list, rowBase);
}

// GEMM2: 10 uniform K=2048 slices. z<8 routed; z=8/9 shared halves.
__global__ __launch_bounds__(256, 2)
void moe_gemm2(const float* __restrict__ sb2, const float* __restrict__ eb2)
{
    int z = blockIdx.z;
    int M, ldA;
    const __half *Ah, *Bh;
    const float *bias, *bias2;
    float* Cf;
    if (z < E_NUM) {
        M = g_counts[z];
        Ah = g_hidr + (long)g_base[z] * F_DIM;
        ldA = F_DIM;
        Bh = g_ew2t + (size_t)z * H_DIM * F_DIM;
        bias = eb2 + z * H_DIM; bias2 = nullptr;
        Cf = g_rout + (long)g_base[z] * H_DIM;
    } else if (z == E_NUM) {
        M = T_TOK;
        Ah = g_hids; ldA = F2;
        Bh = g_sw2t;
        bias = sb2; bias2 = sb2 + H_DIM;
        Cf = g_part0;
    } else {
        M = T_TOK;
        Ah = g_hids + F_DIM; ldA = F2;
        Bh = g_sw2t + (size_t)H_DIM * F_DIM;
        bias = g_zb; bias2 = nullptr;
        Cf = g_part1;
    }
    int rowBase = blockIdx.x * 128;
    if (rowBase >= M) return;
    gemm_core<false>(Ah, Bh, bias, bias2, nullptr, Cf,
                     M, F_DIM, ldA, H_DIM, 0, nullptr, rowBase);
}

// ===================== launch =====================
extern "C" void kernel_launch(void* const* d_in, const int* in_sizes, int n_in,
                              void* d_out, int out_size)
{
    const float* x   = (const float*)d_in[0];
    const float* sw1 = (const float*)d_in[1];
    const float* sb1 = (const float*)d_in[2];
    const float* sw2 = (const float*)d_in[3];
    const float* sb2 = (const float*)d_in[4];
    const float* ew1 = (const float*)d_in[5];
    const float* eb1 = (const float*)d_in[6];
    const float* ew2 = (const float*)d_in[7];
    const float* eb2 = (const float*)d_in[8];
    const float* rw  = (const float*)d_in[9];
    const float* rb  = (const float*)d_in[10];
    float* out = (float*)d_out;

    __half* x_h;
    cudaGetSymbolAddress((void**)&x_h, g_x_h);

    cudaFuncSetAttribute(moe_gemm1, cudaFuncAttributeMaxDynamicSharedMemorySize, DSMEM_BYTES);
    cudaFuncSetAttribute(moe_gemm2, cudaFuncAttributeMaxDynamicSharedMemorySize, DSMEM_BYTES);

    // 1: x conversion + counts zero (must precede router)
    split_kernel<<<(T_TOK * H_DIM / 4 + 255) / 256, 256>>>(x, x_h, T_TOK * H_DIM / 4);
    // 2: router
    router_kernel<<<T_TOK / 4, 128>>>(x, rw, rb);
    // 3: w1 transpose+convert
    tsplitG1<<<dim3(F_DIM / 32, H_DIM / 32, E_NUM + 2), dim3(32, 8)>>>(sw1, ew1);
    // 4: expert bases
    base_kernel<<<1, 32>>>();
    // 5: merged GEMM1 (routed + shared)
    moe_gemm1<<<dim3(T_TOK / 128, F_DIM / 128, E_NUM + 2), 256, DSMEM_BYTES>>>(sb1, eb1);
    // 6: w2 transpose+convert
    tsplitG2<<<dim3(H_DIM / 32, F_DIM / 32, E_NUM + 2), dim3(32, 8)>>>(sw2, ew2);
    // 7: GEMM2, 10 uniform slices
    moe_gemm2<<<dim3(T_TOK / 128, H_DIM / 128, E_NUM + 2), 256, DSMEM_BYTES>>>(sb2, eb2);
    // 8: combine
    combine_kernel<<<T_TOK, 256>>>(out);
}